// round 9
// baseline (speedup 1.0000x reference)
#include <cuda_runtime.h>
#include <math.h>
#include <stdint.h>

#define BB   128
#define TL   2048
#define HH   200
#define HP   256
#define NCTX 16       // context t-chunks
#define KP   224      // padded K
#define NP   208      // padded N rows staged for B
#define NKCH 7        // k chunks of 32
#define SSTR 36       // smem tile stride (floats)

// ---------------- device scratch ----------------
__device__ float d_qp[BB * HP];          // q@Wa.T + ba + bua (padded 0)
__device__ float d_Vap[HP];              // Va padded
__device__ float d_Bp[NP * KP];          // Ua padded, tf32-rounded [n][k]
__device__ float d_scores[BB * TL];
__device__ float d_ctxp[BB * NCTX * HH];

// ---------------- helpers ----------------
__device__ __forceinline__ float tanha(float x) {
    float y; asm("tanh.approx.f32 %0, %1;" : "=f"(y) : "f"(x)); return y;
}
__device__ __forceinline__ float sigf(float x) { return 1.0f / (1.0f + __expf(-x)); }
__device__ __forceinline__ uint32_t smem_u32(const void* p) {
    uint32_t a;
    asm("{ .reg .u64 t; cvta.to.shared.u64 t, %1; cvt.u32.u64 %0, t; }" : "=r"(a) : "l"(p));
    return a;
}
__device__ __forceinline__ void cp16(uint32_t dst, const void* src) {
    asm volatile("cp.async.ca.shared.global [%0], [%1], 16;" :: "r"(dst), "l"(src) : "memory");
}
__device__ __forceinline__ void mma_tf32(float* c, const uint32_t* a, const uint32_t* b) {
    asm volatile("mma.sync.aligned.m16n8k8.row.col.f32.tf32.tf32.f32 "
                 "{%0,%1,%2,%3}, {%4,%5,%6,%7}, {%8,%9}, {%0,%1,%2,%3};"
                 : "+f"(c[0]), "+f"(c[1]), "+f"(c[2]), "+f"(c[3])
                 : "r"(a[0]), "r"(a[1]), "r"(a[2]), "r"(a[3]), "r"(b[0]), "r"(b[1]));
}

// SMEM layout (bytes)
#define SM_QP  0
#define SM_VA  1024
#define SM_RED 2048
#define SM_FR  3072                       // 8*128 floats = 4096
#define SM_A   7168
#define ASZ    (128 * SSTR * 4)           // 18432
#define SM_B   (SM_A + 2 * ASZ)           // 44032
#define BSZ    (NP * SSTR * 4)            // 29952
#define SMEM_SZ (SM_B + 2 * BSZ)          // 103936

extern __shared__ char sm_dyn[];

// ---------------- 1) setup: qp (warp-reduce), Bp tf32, Va ----------------
__global__ void setup_kernel(const float* __restrict__ h0,
                             const float* __restrict__ Wa,
                             const float* __restrict__ ba,
                             const float* __restrict__ Ua,
                             const float* __restrict__ bua,
                             const float* __restrict__ Va) {
    int blk = blockIdx.x;
    int tid = threadIdx.x;
    int lane = tid & 31, wid = tid >> 5;
    if (blk < BB) {
        __shared__ float q[HH];
        for (int k = tid; k < HH; k += 256) q[k] = h0[blk * HH + k];
        __syncthreads();
        for (int h = wid; h < HP; h += 8) {
            if (h < HH) {
                float acc = 0.f;
                const float* w = Wa + h * HH;
                for (int k = lane; k < HH; k += 32) acc += w[k] * q[k];
                #pragma unroll
                for (int o = 16; o; o >>= 1) acc += __shfl_xor_sync(0xffffffffu, acc, o);
                if (lane == 0) d_qp[blk * HP + h] = acc + ba[h] + bua[h];
            } else if (lane == 0) d_qp[blk * HP + h] = 0.f;
        }
    } else {
        int n0 = (blk - BB) * 26;                 // 8 blocks x 26 rows = 208
        for (int idx = tid; idx < 26 * KP; idx += 256) {
            int n = n0 + idx / KP, k = idx % KP;
            float v = (n < HH && k < HH) ? Ua[n * HH + k] : 0.0f;
            uint32_t r;
            asm("cvt.rna.tf32.f32 %0, %1;" : "=r"(r) : "f"(v));
            d_Bp[n * KP + k] = __uint_as_float(r);
        }
        if (blk == BB) {
            for (int h = tid; h < HP; h += 256)
                d_Vap[h] = (h < HH) ? Va[h] : 0.0f;
        }
    }
}

// ---------------- 2) scores: dual-pipe (mma warps + ffma warps) ----------------
__device__ __forceinline__ void stage_chunk(char* smem, uint32_t sb,
                                            const float* encb, int chunk, int buf) {
    int tid = threadIdx.x;
    uint32_t sa  = sb + SM_A + buf * ASZ;
    uint32_t sbb = sb + SM_B + buf * BSZ;
    int kbase = chunk * 32;
    // A: 128 rows x 8 quads = 1024
    #pragma unroll
    for (int it = 0; it < 2; it++) {
        int i = tid + it * 512;
        int m = i >> 3, q = i & 7;
        int k = kbase + q * 4;
        uint32_t dst = sa + (m * SSTR + q * 4) * 4;
        if (k + 3 < HH) {
            cp16(dst, encb + (long)m * HH + k);
        } else {
            *(float4*)(smem + SM_A + buf * ASZ + (m * SSTR + q * 4) * 4) =
                make_float4(0.f, 0.f, 0.f, 0.f);
        }
    }
    // B: 208 rows x 8 quads = 1664
    for (int i = tid; i < NP * 8; i += 512) {
        int n = i >> 3, q = i & 7;
        cp16(sbb + (n * SSTR + q * 4) * 4, d_Bp + n * KP + kbase + q * 4);
    }
    asm volatile("cp.async.commit_group;" ::: "memory");
}

__global__ void __launch_bounds__(512, 1)
scores_mma_kernel(const float* __restrict__ enc) {
    char* smem = sm_dyn;
    uint32_t sb = smem_u32(smem);
    int tid  = threadIdx.x;
    int lane = tid & 31;
    int wid  = tid >> 5;
    int b    = blockIdx.y;
    int t0   = blockIdx.x * 128;

    if (tid < 256) {
        ((float*)(smem + SM_QP))[tid] = d_qp[b * HP + tid];
        ((float*)(smem + SM_VA))[tid] = d_Vap[tid];
    }

    const float* encb = enc + ((long)b * TL + t0) * HH;

    // union accumulator: mma warps use [0..71] as acc[mt][nt][j] = [(mt*9+nt)*4+j]
    //                    ffma warps use [0..31] as facc[mi][j] = [mi*8+j]
    float uacc[72];
    #pragma unroll
    for (int i = 0; i < 72; i++) uacc[i] = 0.0f;

    // mma warp identity
    int wm = wid & 3;          // 0..3 (M)
    int wn = wid >> 2;         // 0..1 for wid<8 (N)
    // ffma warp identity
    int nb = 144 + (wid - 8) * 8;

    stage_chunk(smem, sb, encb, 0, 0);

    #pragma unroll 1
    for (int ch = 0; ch < NKCH; ch++) {
        if (ch + 1 < NKCH) {
            stage_chunk(smem, sb, encb, ch + 1, (ch + 1) & 1);
            asm volatile("cp.async.wait_group 1;" ::: "memory");
        } else {
            asm volatile("cp.async.wait_group 0;" ::: "memory");
        }
        __syncthreads();

        const float* As = (const float*)(smem + SM_A + (ch & 1) * ASZ);
        const float* Bs = (const float*)(smem + SM_B + (ch & 1) * BSZ);

        if (wid < 8) {
            // ---- tensor path: tf32 m16n8k8, 4M x 2N warps, 9 n-tiles each ----
            int g = lane >> 2, c = lane & 3;
            int arow = wm * 32 + g;
            int nrow = wn * 72 + g;
            #pragma unroll
            for (int kt = 0; kt < 4; kt++) {
                int col = kt * 8 + c;
                uint32_t a[2][4];
                #pragma unroll
                for (int mt = 0; mt < 2; mt++) {
                    int r = arow + mt * 16;
                    a[mt][0] = __float_as_uint(As[r * SSTR + col]);
                    a[mt][1] = __float_as_uint(As[(r + 8) * SSTR + col]);
                    a[mt][2] = __float_as_uint(As[r * SSTR + col + 4]);
                    a[mt][3] = __float_as_uint(As[(r + 8) * SSTR + col + 4]);
                }
                #pragma unroll
                for (int nt = 0; nt < 9; nt++) {
                    uint32_t bf[2];
                    int n = nrow + nt * 8;
                    bf[0] = __float_as_uint(Bs[n * SSTR + col]);
                    bf[1] = __float_as_uint(Bs[n * SSTR + col + 4]);
                    mma_tf32(&uacc[(0 * 9 + nt) * 4], a[0], bf);
                    mma_tf32(&uacc[(1 * 9 + nt) * 4], a[1], bf);
                }
            }
        } else {
            // ---- fma path: 8 cols x 128 rows per warp, full-K per-thread dots ----
            #pragma unroll 2
            for (int k = 0; k < 32; k++) {
                float bv[8];
                #pragma unroll
                for (int j = 0; j < 8; j++) bv[j] = Bs[(nb + j) * SSTR + k];
                #pragma unroll
                for (int mi = 0; mi < 4; mi++) {
                    float av = As[(lane + mi * 32) * SSTR + k];
                    #pragma unroll
                    for (int j = 0; j < 8; j++) uacc[mi * 8 + j] += av * bv[j];
                }
            }
        }
        __syncthreads();   // protect buffers from next stage overwrite
    }

    // ---- epilogue ----
    const float* qpS = (const float*)(smem + SM_QP);
    const float* VaS = (const float*)(smem + SM_VA);
    float* red  = (float*)(smem + SM_RED);
    float* fred = (float*)(smem + SM_FR);

    if (wid < 8) {
        int g = lane >> 2, c = lane & 3;
        float rs[4] = {0.f, 0.f, 0.f, 0.f};
        #pragma unroll
        for (int mt = 0; mt < 2; mt++) {
            #pragma unroll
            for (int nt = 0; nt < 9; nt++) {
                int h0i = wn * 72 + nt * 8 + c * 2;
                float va0 = VaS[h0i], va1 = VaS[h0i + 1];
                float q0 = qpS[h0i], q1 = qpS[h0i + 1];
                float* cc = &uacc[(mt * 9 + nt) * 4];
                rs[mt * 2 + 0] += va0 * tanha(q0 + cc[0]) + va1 * tanha(q1 + cc[1]);
                rs[mt * 2 + 1] += va0 * tanha(q0 + cc[2]) + va1 * tanha(q1 + cc[3]);
            }
        }
        #pragma unroll
        for (int j = 0; j < 4; j++) {
            rs[j] += __shfl_xor_sync(0xffffffffu, rs[j], 1);
            rs[j] += __shfl_xor_sync(0xffffffffu, rs[j], 2);
        }
        if (c == 0) {
            int q = lane >> 2;
            red[wn * 128 + wm * 32 + q]      = rs[0];
            red[wn * 128 + wm * 32 + q + 8]  = rs[1];
            red[wn * 128 + wm * 32 + q + 16] = rs[2];
            red[wn * 128 + wm * 32 + q + 24] = rs[3];
        }
    } else {
        #pragma unroll
        for (int mi = 0; mi < 4; mi++) {
            float ps = 0.f;
            #pragma unroll
            for (int j = 0; j < 8; j++) {
                int n = nb + j;
                ps += VaS[n] * tanha(qpS[n] + uacc[mi * 8 + j]);
            }
            fred[(wid - 8) * 128 + lane + mi * 32] = ps;
        }
    }
    __syncthreads();
    if (tid < 128) {
        float s = red[tid] + red[128 + tid];
        #pragma unroll
        for (int w = 0; w < 8; w++) s += fred[w * 128 + tid];
        d_scores[(long)b * TL + t0 + tid] = s;   // bva shift cancels in softmax
    }
}

// ---------------- 3) softmax over T, in place ----------------
__global__ void softmax_kernel() {
    __shared__ float red[256];
    int b = blockIdx.x, tid = threadIdx.x;
    float* row = d_scores + (long)b * TL;

    float m = -1e30f;
    for (int i = tid; i < TL; i += 256) m = fmaxf(m, row[i]);
    red[tid] = m; __syncthreads();
    for (int s = 128; s; s >>= 1) { if (tid < s) red[tid] = fmaxf(red[tid], red[tid + s]); __syncthreads(); }
    m = red[0]; __syncthreads();

    float sum = 0.0f;
    for (int i = tid; i < TL; i += 256) {
        float e = __expf(row[i] - m);
        row[i] = e; sum += e;
    }
    red[tid] = sum; __syncthreads();
    for (int s = 128; s; s >>= 1) { if (tid < s) red[tid] += red[tid + s]; __syncthreads(); }
    float inv = 1.0f / red[0];

    for (int i = tid; i < TL; i += 256) row[i] *= inv;
}

// ---------------- 4) context = attn @ enc (float2, 128-row chunks) ----------------
__global__ void __launch_bounds__(128) context_kernel(const float* __restrict__ enc) {
    __shared__ float at[128];
    int tc = blockIdx.x;
    int b  = blockIdx.y;
    int tid = threadIdx.x;
    at[tid] = d_scores[(long)b * TL + tc * 128 + tid];
    __syncthreads();
    if (tid < 100) {
        const float* e = enc + ((long)b * TL + tc * 128) * HH + 2 * tid;
        float a0 = 0, a1 = 0, b0 = 0, b1 = 0, c0 = 0, c1 = 0, d0 = 0, d1 = 0;
        #pragma unroll 2
        for (int t = 0; t < 128; t += 4) {
            float2 v0 = *(const float2*)(e + (long)t * HH);
            float2 v1 = *(const float2*)(e + (long)(t + 1) * HH);
            float2 v2 = *(const float2*)(e + (long)(t + 2) * HH);
            float2 v3 = *(const float2*)(e + (long)(t + 3) * HH);
            a0 += at[t] * v0.x;     a1 += at[t] * v0.y;
            b0 += at[t + 1] * v1.x; b1 += at[t + 1] * v1.y;
            c0 += at[t + 2] * v2.x; c1 += at[t + 2] * v2.y;
            d0 += at[t + 3] * v3.x; d1 += at[t + 3] * v3.y;
        }
        float* dst = d_ctxp + ((long)b * NCTX + tc) * HH + 2 * tid;
        dst[0] = (a0 + b0) + (c0 + d0);
        dst[1] = (a1 + b1) + (c1 + d1);
    }
}

// ---------------- 5) decoder: combine + 5 LSTM+MLP steps, 4 b per block ----------------
__global__ void __launch_bounds__(256) decoder_kernel(
        const float* __restrict__ x,
        const float* __restrict__ h0,
        const float* __restrict__ c0,
        const float* __restrict__ W_ih,
        const float* __restrict__ W_hh,
        const float* __restrict__ b_ih,
        const float* __restrict__ b_hh,
        const float* __restrict__ W1, const float* __restrict__ b1,
        const float* __restrict__ W2, const float* __restrict__ b2,
        const float* __restrict__ W3, const float* __restrict__ b3,
        float* __restrict__ out) {
    __shared__ float ctx4[4][HH];
    __shared__ float h04[4][HH];
    __shared__ float gb4[4][800];
    __shared__ float r[HH];
    __shared__ float s1[100];
    __shared__ float s2[64];
    __shared__ float xb;
    int tid = threadIdx.x;
    int bs0 = blockIdx.x * 4;

    for (int bl = 0; bl < 4; bl++) {
        int b = bs0 + bl;
        if (tid < HH) {
            float s = 0.f;
            #pragma unroll
            for (int i = 0; i < NCTX; i++)
                s += d_ctxp[((long)b * NCTX + i) * HH + tid];
            ctx4[bl][tid] = s;
        }
    }
    for (int i = tid; i < 4 * HH; i += 256)
        h04[i / HH][i % HH] = h0[(bs0 + i / HH) * HH + i % HH];
    __syncthreads();

    for (int g = tid; g < 800; g += 256) {
        float bias = b_ih[g] + b_hh[g];
        float a0 = bias, a1 = bias, a2 = bias, a3 = bias;
        const float* wh = W_hh + g * HH;
        #pragma unroll 4
        for (int k = 0; k < HH; k++) {
            float wv = wh[k];
            a0 += wv * h04[0][k]; a1 += wv * h04[1][k];
            a2 += wv * h04[2][k]; a3 += wv * h04[3][k];
        }
        const float* wi = W_ih + g * 201 + 1;
        #pragma unroll 4
        for (int k = 0; k < HH; k++) {
            float wv = wi[k];
            a0 += wv * ctx4[0][k]; a1 += wv * ctx4[1][k];
            a2 += wv * ctx4[2][k]; a3 += wv * ctx4[3][k];
        }
        gb4[0][g] = a0; gb4[1][g] = a1; gb4[2][g] = a2; gb4[3][g] = a3;
    }
    __syncthreads();

    for (int bl = 0; bl < 4; bl++) {
        int b = bs0 + bl;
        if (tid == 0) xb = x[b];
        __syncthreads();
        for (int step = 0; step < 5; step++) {
            if (tid < HH) {
                float xv = xb;
                float gi = gb4[bl][tid]       + W_ih[tid * 201]         * xv;
                float gf = gb4[bl][200 + tid] + W_ih[(200 + tid) * 201] * xv;
                float gg = gb4[bl][400 + tid] + W_ih[(400 + tid) * 201] * xv;
                float go = gb4[bl][600 + tid] + W_ih[(600 + tid) * 201] * xv;
                float cp = c0[b * HH + tid];
                float cn = sigf(gf) * cp + sigf(gi) * tanhf(gg);
                float hn = sigf(go) * tanhf(cn);
                r[tid] = fmaxf(hn, 0.0f);
            }
            __syncthreads();
            if (tid < 100) {
                float acc = b1[tid];
                const float* wr = W1 + tid * HH;
                #pragma unroll 4
                for (int k = 0; k < HH; k++) acc += wr[k] * r[k];
                s1[tid] = fmaxf(acc, 0.0f);
            }
            __syncthreads();
            if (tid < 50) {
                float acc = b2[tid];
                const float* wr = W2 + tid * 100;
                #pragma unroll 4
                for (int k = 0; k < 100; k++) acc += wr[k] * s1[k];
                s2[tid] = fmaxf(acc, 0.0f);
            }
            __syncthreads();
            if (tid == 0) {
                float acc = b3[0];
                #pragma unroll
                for (int k = 0; k < 50; k++) acc += W3[k] * s2[k];
                out[b * 5 + step] = acc;
                xb = acc;
            }
            __syncthreads();
        }
    }
}

// ---------------- launch ----------------
extern "C" void kernel_launch(void* const* d_in, const int* in_sizes, int n_in,
                              void* d_out, int out_size) {
    const float* x    = (const float*)d_in[0];
    const float* h0   = (const float*)d_in[1];
    const float* c0   = (const float*)d_in[2];
    const float* enc  = (const float*)d_in[3];
    const float* Wa   = (const float*)d_in[4];
    const float* ba   = (const float*)d_in[5];
    const float* Ua   = (const float*)d_in[6];
    const float* bua  = (const float*)d_in[7];
    const float* Va   = (const float*)d_in[8];
    const float* bva  = (const float*)d_in[9];
    const float* W_ih = (const float*)d_in[10];
    const float* W_hh = (const float*)d_in[11];
    const float* b_ih = (const float*)d_in[12];
    const float* b_hh = (const float*)d_in[13];
    const float* W1   = (const float*)d_in[14];
    const float* b1   = (const float*)d_in[15];
    const float* W2   = (const float*)d_in[16];
    const float* b2   = (const float*)d_in[17];
    const float* W3   = (const float*)d_in[18];
    const float* b3   = (const float*)d_in[19];
    float* out = (float*)d_out;
    (void)bva;

    cudaFuncSetAttribute(scores_mma_kernel,
                         cudaFuncAttributeMaxDynamicSharedMemorySize, SMEM_SZ);

    setup_kernel<<<BB + 8, 256>>>(h0, Wa, ba, Ua, bua, Va);
    scores_mma_kernel<<<dim3(TL / 128, BB), 512, SMEM_SZ>>>(enc);
    softmax_kernel<<<BB, 256>>>();
    context_kernel<<<dim3(NCTX, BB), 128>>>(enc);
    decoder_kernel<<<BB / 4, 256>>>(x, h0, c0, W_ih, W_hh, b_ih, b_hh,
                                    W1, b1, W2, b2, W3, b3, out);
}